// round 12
// baseline (speedup 1.0000x reference)
#include <cuda_runtime.h>
#include <math.h>
#include <stdint.h>

#define R_TOT 16384
#define WD 768
#define NHEADS 12
#define HDIM 64
#define NMB 256
#define MB 16
#define SEQ 4096
#define NB 4
#define LN_EPS 1e-6f

// ---------------- scratch (device globals; no allocation allowed) -------------
__device__ float g_xqk [R_TOT * WD];                 // hidden@wq
__device__ float g_xv  [R_TOT * WD];                 // hidden@wv
__device__ float g_gate[R_TOT * WD];                 // hidden@wg (pre-gelu)
__device__ float g_XQ  [NB * NHEADS * NMB * MB * HDIM];
__device__ float g_XK  [NB * NHEADS * NMB * MB * HDIM];
__device__ float g_XVr [NB * NHEADS * NMB * MB * HDIM];
__device__ float g_lr  [NB * NHEADS * NMB * MB];
__device__ float g_scan[R_TOT * WD];
__device__ float g_Ah  [R_TOT * WD];                 // pre-split A (hi)
__device__ float g_Al  [R_TOT * WD];                 // pre-split A (lo)
__device__ float g_Bh  [WD * WD];                    // pre-split weight (hi)
__device__ float g_Bl  [WD * WD];                    // pre-split weight (lo)

// ============ tf32 split helpers ==============================================
__device__ __forceinline__ void split_tf32s(float x, float& h, float& l) {
    asm("cvt.rna.tf32.f32 %0, %1;" : "=f"(h) : "f"(x));
    float r = x - h;
    asm("cvt.rna.tf32.f32 %0, %1;" : "=f"(l) : "f"(r));
}

__global__ __launch_bounds__(256) void split_kernel(
    const float* __restrict__ in, float* __restrict__ hi, float* __restrict__ lo, int n4)
{
    int i = blockIdx.x * blockDim.x + threadIdx.x;
    if (i >= n4) return;
    float4 v = ((const float4*)in)[i];
    float4 h, l;
    split_tf32s(v.x, h.x, l.x);
    split_tf32s(v.y, h.y, l.y);
    split_tf32s(v.z, h.z, l.z);
    split_tf32s(v.w, h.w, l.w);
    ((float4*)hi)[i] = h;
    ((float4*)lo)[i] = l;
}

__device__ __forceinline__ void mma_tf32(float* c, const uint32_t* a, const uint32_t* b) {
    asm volatile(
        "mma.sync.aligned.m16n8k8.row.col.f32.tf32.tf32.f32 "
        "{%0,%1,%2,%3}, {%4,%5,%6,%7}, {%8,%9}, {%0,%1,%2,%3};"
        : "+f"(c[0]), "+f"(c[1]), "+f"(c[2]), "+f"(c[3])
        : "r"(a[0]), "r"(a[1]), "r"(a[2]), "r"(a[3]), "r"(b[0]), "r"(b[1]));
}

#define CP16(smem_u32, gptr) \
    asm volatile("cp.async.cg.shared.global [%0], [%1], 16;" :: "r"(smem_u32), "l"(gptr))

#define SA_STRIDE 20
#define SB_STRIDE 136
// dynamic smem (floats): sAh[2][2560] @0, sAl @5120, sBh[2][2176] @10240, sBl @14592
#define SMEM_FLOATS 18944
#define GEMM_SMEM_BYTES (SMEM_FLOATS * 4)

// ===== tensor-core GEMM on pre-split operands: C = (Ah+Al)@(Bh+Bl) (3 terms) ==
// Single barrier per k-tile: wait_group(0) -> syncthreads -> prefetch kt+1 -> MMA kt.
__global__ __launch_bounds__(256, 2) void gemm_tf32_kernel(
    const float* __restrict__ Ahg, const float* __restrict__ Alg,
    const float* __restrict__ Bhg, const float* __restrict__ Blg,
    float* __restrict__ C, int M, int N, int K)
{
    extern __shared__ float smem[];
    float* sAh = smem;
    float* sAl = smem + 5120;
    float* sBh = smem + 10240;
    float* sBl = smem + 14592;

    const int tid  = threadIdx.x;
    const int wid  = tid >> 5;
    const int lane = tid & 31;
    const int lr   = lane >> 2;
    const int lc   = lane & 3;
    const int warpM = wid >> 2;     // 0..1  -> 64 rows
    const int warpN = wid & 3;      // 0..3  -> 32 cols

    const int NT = K / 16;

    const size_t aOff = (size_t)(blockIdx.y * 128) * K;
    const int    bOff = blockIdx.x * 128;

    uint32_t uAh = (uint32_t)__cvta_generic_to_shared(sAh);
    uint32_t uAl = (uint32_t)__cvta_generic_to_shared(sAl);
    uint32_t uBh = (uint32_t)__cvta_generic_to_shared(sBh);
    uint32_t uBl = (uint32_t)__cvta_generic_to_shared(sBl);

    const int aRow0 = tid >> 2;            // 0..63 (and +64)
    const int aC4   = (tid & 3) * 4;
    const int bRow0 = tid >> 5;            // 0..7 (and +8)
    const int bC4   = (tid & 31) * 4;

    float acc[4][4][4];
#pragma unroll
    for (int m = 0; m < 4; m++)
#pragma unroll
        for (int n = 0; n < 4; n++)
#pragma unroll
            for (int e = 0; e < 4; e++) acc[m][n][e] = 0.f;

    // ---- prologue: stage 0 ----
    {
        size_t ai = aOff + (size_t)aRow0 * K + aC4;
        CP16(uAh + (aRow0 * SA_STRIDE + aC4) * 4, Ahg + ai);
        CP16(uAh + ((aRow0 + 64) * SA_STRIDE + aC4) * 4, Ahg + ai + (size_t)64 * K);
        CP16(uAl + (aRow0 * SA_STRIDE + aC4) * 4, Alg + ai);
        CP16(uAl + ((aRow0 + 64) * SA_STRIDE + aC4) * 4, Alg + ai + (size_t)64 * K);
        size_t bi = (size_t)bRow0 * N + bOff + bC4;
        CP16(uBh + (bRow0 * SB_STRIDE + bC4) * 4, Bhg + bi);
        CP16(uBh + ((bRow0 + 8) * SB_STRIDE + bC4) * 4, Bhg + bi + (size_t)8 * N);
        CP16(uBl + (bRow0 * SB_STRIDE + bC4) * 4, Blg + bi);
        CP16(uBl + ((bRow0 + 8) * SB_STRIDE + bC4) * 4, Blg + bi + (size_t)8 * N);
        asm volatile("cp.async.commit_group;");
    }

    for (int kt = 0; kt < NT; kt++) {
        const int cur = kt & 1;
        asm volatile("cp.async.wait_group 0;");
        __syncthreads();

        // prefetch kt+1 into the other buffer (read last at compute kt-1, safe)
        if (kt + 1 < NT) {
            const int nxt = (kt + 1) & 1;
            uint32_t oA = nxt * 128 * SA_STRIDE * 4;
            uint32_t oB = nxt * 16 * SB_STRIDE * 4;
            size_t ai = aOff + (size_t)aRow0 * K + (kt + 1) * 16 + aC4;
            CP16(uAh + oA + (aRow0 * SA_STRIDE + aC4) * 4, Ahg + ai);
            CP16(uAh + oA + ((aRow0 + 64) * SA_STRIDE + aC4) * 4, Ahg + ai + (size_t)64 * K);
            CP16(uAl + oA + (aRow0 * SA_STRIDE + aC4) * 4, Alg + ai);
            CP16(uAl + oA + ((aRow0 + 64) * SA_STRIDE + aC4) * 4, Alg + ai + (size_t)64 * K);
            size_t bi = (size_t)((kt + 1) * 16 + bRow0) * N + bOff + bC4;
            CP16(uBh + oB + (bRow0 * SB_STRIDE + bC4) * 4, Bhg + bi);
            CP16(uBh + oB + ((bRow0 + 8) * SB_STRIDE + bC4) * 4, Bhg + bi + (size_t)8 * N);
            CP16(uBl + oB + (bRow0 * SB_STRIDE + bC4) * 4, Blg + bi);
            CP16(uBl + oB + ((bRow0 + 8) * SB_STRIDE + bC4) * 4, Blg + bi + (size_t)8 * N);
            asm volatile("cp.async.commit_group;");
        }

        const float* cAh = sAh + cur * 128 * SA_STRIDE;
        const float* cAl = sAl + cur * 128 * SA_STRIDE;
        const float* cBh = sBh + cur * 16 * SB_STRIDE;
        const float* cBl = sBl + cur * 16 * SB_STRIDE;
#pragma unroll
        for (int ks = 0; ks < 2; ks++) {
            uint32_t ahi[4][4], alo[4][4];
#pragma unroll
            for (int m = 0; m < 4; m++) {
                int r0 = warpM * 64 + m * 16 + lr;
                int c0 = ks * 8 + lc;
                ahi[m][0] = __float_as_uint(cAh[r0 * SA_STRIDE + c0]);
                ahi[m][1] = __float_as_uint(cAh[(r0 + 8) * SA_STRIDE + c0]);
                ahi[m][2] = __float_as_uint(cAh[r0 * SA_STRIDE + c0 + 4]);
                ahi[m][3] = __float_as_uint(cAh[(r0 + 8) * SA_STRIDE + c0 + 4]);
                alo[m][0] = __float_as_uint(cAl[r0 * SA_STRIDE + c0]);
                alo[m][1] = __float_as_uint(cAl[(r0 + 8) * SA_STRIDE + c0]);
                alo[m][2] = __float_as_uint(cAl[r0 * SA_STRIDE + c0 + 4]);
                alo[m][3] = __float_as_uint(cAl[(r0 + 8) * SA_STRIDE + c0 + 4]);
            }
            uint32_t bhi[4][2], blo[4][2];
#pragma unroll
            for (int n = 0; n < 4; n++) {
                int cc = warpN * 32 + n * 8 + lr;
                int r0 = ks * 8 + lc;
                bhi[n][0] = __float_as_uint(cBh[r0 * SB_STRIDE + cc]);
                bhi[n][1] = __float_as_uint(cBh[(r0 + 4) * SB_STRIDE + cc]);
                blo[n][0] = __float_as_uint(cBl[r0 * SB_STRIDE + cc]);
                blo[n][1] = __float_as_uint(cBl[(r0 + 4) * SB_STRIDE + cc]);
            }
            // term-major issue: 16 independent MMAs between accumulator reuses
#pragma unroll
            for (int m = 0; m < 4; m++)
#pragma unroll
                for (int n = 0; n < 4; n++)
                    mma_tf32(acc[m][n], ahi[m], bhi[n]);
#pragma unroll
            for (int m = 0; m < 4; m++)
#pragma unroll
                for (int n = 0; n < 4; n++)
                    mma_tf32(acc[m][n], ahi[m], blo[n]);
#pragma unroll
            for (int m = 0; m < 4; m++)
#pragma unroll
                for (int n = 0; n < 4; n++)
                    mma_tf32(acc[m][n], alo[m], bhi[n]);
        }
    }

    // ---- epilogue ----
#pragma unroll
    for (int m = 0; m < 4; m++) {
        int row = blockIdx.y * 128 + warpM * 64 + m * 16 + lr;
#pragma unroll
        for (int n = 0; n < 4; n++) {
            int col = blockIdx.x * 128 + warpN * 32 + n * 8 + 2 * lc;
            float* cp = C + (size_t)row * N + col;
            *(float2*)cp = make_float2(acc[m][n][0], acc[m][n][1]);
            *(float2*)(cp + (size_t)8 * N) = make_float2(acc[m][n][2], acc[m][n][3]);
        }
    }
}

// ---------------- ttt_lr ------------------------------------------------------
__global__ __launch_bounds__(256) void lr_kernel(
    const float* __restrict__ hidden, const float* __restrict__ lrk,
    const float* __restrict__ lrb, float* __restrict__ out)
{
    int row = blockIdx.x * 8 + (threadIdx.x >> 5);
    int lane = threadIdx.x & 31;
    if (row >= R_TOT) return;
    const float* hr = hidden + (size_t)row * WD;
    float acc[NHEADS];
#pragma unroll
    for (int h = 0; h < NHEADS; h++) acc[h] = 0.f;
    for (int w = lane; w < WD; w += 32) {
        float hv = hr[w];
#pragma unroll
        for (int h = 0; h < NHEADS; h++) acc[h] += hv * lrk[h * WD + w];
    }
#pragma unroll
    for (int h = 0; h < NHEADS; h++) {
#pragma unroll
        for (int o = 16; o > 0; o >>= 1)
            acc[h] += __shfl_xor_sync(0xffffffffu, acc[h], o);
    }
    if (lane < NHEADS) {
        float x = acc[lane] + lrb[lane];
        float v = (1.0f / (1.0f + expf(-x))) * (1.0f / 64.0f);
        int b = row >> 12;
        int n = row & 4095;
        int nm = n >> 4, m = n & 15;
        out[(((size_t)b * NHEADS + lane) * NMB + nm) * MB + m] = v;
    }
}

// ---------------- causal dwconv(width 4) + RoPE + reorder ---------------------
__global__ __launch_bounds__(256) void convrope_kernel(
    const float* __restrict__ xqk, const float* __restrict__ xv,
    const float* __restrict__ kq, const float* __restrict__ bq,
    const float* __restrict__ kk, const float* __restrict__ bk,
    float* __restrict__ XQr, float* __restrict__ XKr, float* __restrict__ XVr)
{
    int idx = blockIdx.x * blockDim.x + threadIdx.x;
    if (idx >= R_TOT * 384) return;
    int c2 = idx % 384;
    int row = idx / 384;
    int c = c2 * 2;
    int n = row & 4095;
    int b = row >> 12;

    float q0 = bq[c], q1 = bq[c + 1];
    float k0 = bk[c], k1 = bk[c + 1];
#pragma unroll
    for (int t = 0; t < 4; t++) {
        int nn = n - 3 + t;
        if (nn >= 0) {
            const float* xr = xqk + ((size_t)(b * SEQ + nn)) * WD + c;
            float x0 = xr[0], x1 = xr[1];
            q0 += kq[t * WD + c] * x0;     q1 += kq[t * WD + c + 1] * x1;
            k0 += kk[t * WD + c] * x0;     k1 += kk[t * WD + c + 1] * x1;
        }
    }
    int h = c >> 6;
    int d = c & 63;
    int fi = d >> 1;
    int pos = n & 15;
    float freq = exp2f(-((float)(2 * fi) * (1.0f / 64.0f)) * 13.2877123795f);
    float ang = (float)pos * freq;
    float cs = cosf(ang), sn = sinf(ang);

    float qe = q0 * cs - q1 * sn;
    float qo = q0 * sn + q1 * cs;
    float ke = k0 * cs - k1 * sn;
    float ko = k0 * sn + k1 * cs;

    int nm = n >> 4, m = n & 15;
    size_t off = ((((size_t)b * NHEADS + h) * NMB + nm) * MB + m) * HDIM + d;
    XQr[off] = qe;  XQr[off + 1] = qo;
    XKr[off] = ke;  XKr[off + 1] = ko;
    const float* xvp = xv + (size_t)row * WD + c;
    XVr[off] = xvp[0];  XVr[off + 1] = xvp[1];
}

// ---------------- the TTT scan ------------------------------------------------
#define XS 68   // XQ/XK tile row stride

__global__ __launch_bounds__(256) void scan_kernel(
    const float* __restrict__ W1g, const float* __restrict__ b1g,
    const float* __restrict__ glng, const float* __restrict__ blng,
    const float* __restrict__ lti,
    const float* __restrict__ XQg, const float* __restrict__ XKg,
    const float* __restrict__ XVg, const float* __restrict__ lrg,
    float* __restrict__ scan_out)
{
    __shared__ float W1s[64 * 64];
    __shared__ float b1s[64];
    __shared__ float XQs[16 * XS];
    __shared__ float XKs[16 * XS];
    __shared__ float Ts [16 * 64];
    __shared__ float grads[16 * 64];
    __shared__ float Attns[16 * 17];
    __shared__ float lrs[16];
    __shared__ float tis[16];
    __shared__ float gln[64], bln[64];

    const int bh = blockIdx.x;
    const int h = bh % NHEADS;
    const int b = bh / NHEADS;
    const int t = threadIdx.x;

    {
        const float* w1p = W1g + (size_t)h * 64 * 64;
        for (int j = t; j < 4096; j += 256) W1s[j] = w1p[j];
        if (t < 64) {
            b1s[t] = b1g[h * 64 + t];
            gln[t] = glng[h * 64 + t];
            bln[t] = blng[h * 64 + t];
        }
        if (t < 16) tis[t] = fmaxf(1.0f / (float)(t + 1) + lti[t], 0.0f);
    }
    __syncthreads();

    const int i  = t >> 4;
    const int cg = t & 15;
    const int d0 = cg * 4;

    const float gv0 = gln[d0], gv1 = gln[d0 + 1], gv2 = gln[d0 + 2], gv3 = gln[d0 + 3];
    const float bv0 = bln[d0], bv1 = bln[d0 + 1], bv2 = bln[d0 + 2], bv3 = bln[d0 + 3];
    const float ti_i = tis[i];
    const float le15 = tis[15];

    const float* XQb = XQg + (size_t)bh * NMB * MB * HDIM;
    const float* XKb = XKg + (size_t)bh * NMB * MB * HDIM;
    const float* XVb = XVg + (size_t)bh * NMB * MB * HDIM;
    const float* lrbp = lrg + (size_t)bh * NMB * MB;
    float* outb = scan_out + (size_t)b * SEQ * WD + h * HDIM;

    size_t tb = (size_t)i * HDIM + d0;
    float4 q4 = *(const float4*)(XQb + tb);
    float4 k4 = *(const float4*)(XKb + tb);
    float4 v4 = *(const float4*)(XVb + tb);
    float lrv = (t < 16) ? lrbp[t] : 0.f;

    for (int s = 0; s < NMB; s++) {
        *(float4*)&XQs[i * XS + d0] = q4;
        *(float4*)&XKs[i * XS + d0] = k4;
        *(float4*)&Ts[i * 64 + d0] = make_float4(v4.x - k4.x, v4.y - k4.y, v4.z - k4.z, v4.w - k4.w);
        if (t < 16) lrs[t] = lrv;
        __syncthreads();                               // A

        float4 q4n, k4n, v4n; float lrvn = 0.f;
        if (s + 1 < NMB) {
            size_t tb2 = (size_t)(s + 1) * MB * HDIM + i * HDIM + d0;
            q4n = *(const float4*)(XQb + tb2);
            k4n = *(const float4*)(XKb + tb2);
            v4n = *(const float4*)(XVb + tb2);
            if (t < 16) lrvn = lrbp[(s + 1) * MB + t];
        }

        float b1x = b1s[d0], b1y = b1s[d0 + 1], b1z = b1s[d0 + 2], b1w = b1s[d0 + 3];
        float zx = b1x, zy = b1y, zz = b1z, zw = b1w;
        float ax = b1x, ay = b1y, az = b1z, aw = b1w;
        float at = 0.f;
#pragma unroll
        for (int k0 = 0; k0 < 64; k0 += 4) {
            float4 xkv = *(const float4*)&XKs[i * XS + k0];
            float4 xqv = *(const float4*)&XQs[i * XS + k0];
            float4 xka = *(const float4*)&XKs[cg * XS + k0];
            at += xqv.x * xka.x + xqv.y * xka.y + xqv.z * xka.z + xqv.w * xka.w;
            {
                float4 w = *(const float4*)&W1s[(k0 + 0) * 64 + d0];
                zx += xkv.x * w.x; zy += xkv.x * w.y; zz += xkv.x * w.z; zw += xkv.x * w.w;
                ax += xqv.x * w.x; ay += xqv.x * w.y; az += xqv.x * w.z; aw += xqv.x * w.w;
            }
            {
                float4 w = *(const float4*)&W1s[(k0 + 1) * 64 + d0];
                zx += xkv.y * w.x; zy += xkv.y * w.y; zz += xkv.y * w.z; zw += xkv.y * w.w;
                ax += xqv.y * w.x; ay += xqv.y * w.y; az += xqv.y * w.z; aw += xqv.y * w.w;
            }
            {
                float4 w = *(const float4*)&W1s[(k0 + 2) * 64 + d0];
                zx += xkv.z * w.x; zy += xkv.z * w.y; zz += xkv.z * w.z; zw += xkv.z * w.w;
                ax += xqv.z * w.x; ay += xqv.z * w.y; az += xqv.z * w.z; aw += xqv.z * w.w;
            }
            {
                float4 w = *(const float4*)&W1s[(k0 + 3) * 64 + d0];
                zx += xkv.w * w.x; zy += xkv.w * w.y; zz += xkv.w * w.z; zw += xkv.w * w.w;
                ax += xqv.w * w.x; ay += xqv.w * w.y; az += xqv.w * w.z; aw += xqv.w * w.w;
            }
        }
        Attns[i * 17 + cg] = at;

        float sum = zx + zy + zz + zw;
        sum += __shfl_xor_sync(0xffffffffu, sum, 1);
        sum += __shfl_xor_sync(0xffffffffu, sum, 2);
        sum += __shfl_xor_sync(0xffffffffu, sum, 4);
        sum += __shfl_xor_sync(0xffffffffu, sum, 8);
        float mu = sum * (1.0f / 64.0f);
        float cx = zx - mu, cy = zy - mu, cz = zz - mu, cw = zw - mu;
        float s2 = cx * cx + cy * cy + cz * cz + cw * cw;
        s2 += __shfl_xor_sync(0xffffffffu, s2, 1);
        s2 += __shfl_xor_sync(0xffffffffu, s2, 2);
        s2 += __shfl_xor_sync(0xffffffffu, s2, 4);
        s2 += __shfl_xor_sync(0xffffffffu, s2, 8);
        float istd = 1.0f / sqrtf(s2 * (1.0f / 64.0f) + LN_EPS);
        float xh0 = cx * istd, xh1 = cy * istd, xh2 = cz * istd, xh3 = cw * istd;
        float4 tt = *(const float4*)&Ts[i * 64 + d0];
        float g0 = (gv0 * xh0 + bv0 - tt.x) * gv0;
        float g1 = (gv1 * xh1 + bv1 - tt.y) * gv1;
        float g2 = (gv2 * xh2 + bv2 - tt.z) * gv2;
        float g3 = (gv3 * xh3 + bv3 - tt.w) * gv3;
        float sg = g0 + g1 + g2 + g3;
        sg += __shfl_xor_sync(0xffffffffu, sg, 1);
        sg += __shfl_xor_sync(0xffffffffu, sg, 2);
        sg += __shfl_xor_sync(0xffffffffu, sg, 4);
        sg += __shfl_xor_sync(0xffffffffu, sg, 8);
        float sgx = g0 * xh0 + g1 * xh1 + g2 * xh2 + g3 * xh3;
        sgx += __shfl_xor_sync(0xffffffffu, sgx, 1);
        sgx += __shfl_xor_sync(0xffffffffu, sgx, 2);
        sgx += __shfl_xor_sync(0xffffffffu, sgx, 4);
        sgx += __shfl_xor_sync(0xffffffffu, sgx, 8);
        float cf = istd * (1.0f / 64.0f);
        *(float4*)&grads[i * 64 + d0] = make_float4(
            (64.f * g0 - sg - xh0 * sgx) * cf,
            (64.f * g1 - sg - xh1 * sgx) * cf,
            (64.f * g2 - sg - xh2 * sgx) * cf,
            (64.f * g3 - sg - xh3 * sgx) * cf);
        __syncthreads();                               // B

        for (int jj = 0; jj <= i; jj++) {
            float c = ti_i * lrs[jj] * (Attns[i * 17 + jj] + 1.0f);
            float4 gr = *(const float4*)&grads[jj * 64 + d0];
            ax -= c * gr.x;  ay -= c * gr.y;  az -= c * gr.z;  aw -= c * gr.w;
        }
        float su = ax + ay + az + aw;
        su += __shfl_xor_sync(0xffffffffu, su, 1);
        su += __shfl_xor_sync(0xffffffffu, su, 2);
        su += __shfl_xor_sync(0xffffffffu, su, 4);
        su += __shfl_xor_sync(0xffffffffu, su, 8);
        float mu2 = su * (1.0f / 64.0f);
        float ex = ax - mu2, ey = ay - mu2, ez = az - mu2, ew = aw - mu2;
        float v2 = ex * ex + ey * ey + ez * ez + ew * ew;
        v2 += __shfl_xor_sync(0xffffffffu, v2, 1);
        v2 += __shfl_xor_sync(0xffffffffu, v2, 2);
        v2 += __shfl_xor_sync(0xffffffffu, v2, 4);
        v2 += __shfl_xor_sync(0xffffffffu, v2, 8);
        float istd2 = 1.0f / sqrtf(v2 * (1.0f / 64.0f) + LN_EPS);
        *(float4*)(outb + (size_t)(s * MB + i) * WD + d0) = make_float4(
            q4.x + gv0 * (ex * istd2) + bv0,
            q4.y + gv1 * (ey * istd2) + bv1,
            q4.z + gv2 * (ez * istd2) + bv2,
            q4.w + gv3 * (ew * istd2) + bv3);

        {
            float4 w0 = *(const float4*)&W1s[(4 * i + 0) * 64 + d0];
            float4 w1 = *(const float4*)&W1s[(4 * i + 1) * 64 + d0];
            float4 w2 = *(const float4*)&W1s[(4 * i + 2) * 64 + d0];
            float4 w3 = *(const float4*)&W1s[(4 * i + 3) * 64 + d0];
#pragma unroll
            for (int ii = 0; ii < 16; ii++) {
                float lg = le15 * lrs[ii];
                float4 xk4 = *(const float4*)&XKs[ii * XS + 4 * i];
                float4 gr  = *(const float4*)&grads[ii * 64 + d0];
                float c0 = lg * xk4.x, c1 = lg * xk4.y, c2 = lg * xk4.z, c3 = lg * xk4.w;
                w0.x -= c0 * gr.x; w0.y -= c0 * gr.y; w0.z -= c0 * gr.z; w0.w -= c0 * gr.w;
                w1.x -= c1 * gr.x; w1.y -= c1 * gr.y; w1.z -= c1 * gr.z; w1.w -= c1 * gr.w;
                w2.x -= c2 * gr.x; w2.y -= c2 * gr.y; w2.z -= c2 * gr.z; w2.w -= c2 * gr.w;
                w3.x -= c3 * gr.x; w3.y -= c3 * gr.y; w3.z -= c3 * gr.z; w3.w -= c3 * gr.w;
            }
            *(float4*)&W1s[(4 * i + 0) * 64 + d0] = w0;
            *(float4*)&W1s[(4 * i + 1) * 64 + d0] = w1;
            *(float4*)&W1s[(4 * i + 2) * 64 + d0] = w2;
            *(float4*)&W1s[(4 * i + 3) * 64 + d0] = w3;
        }
        if (i == 0) {
            float4 bb = *(const float4*)&b1s[d0];
#pragma unroll
            for (int ii = 0; ii < 16; ii++) {
                float lg = le15 * lrs[ii];
                float4 gr = *(const float4*)&grads[ii * 64 + d0];
                bb.x -= lg * gr.x; bb.y -= lg * gr.y; bb.z -= lg * gr.z; bb.w -= lg * gr.w;
            }
            *(float4*)&b1s[d0] = bb;
        }

        q4 = q4n; k4 = k4n; v4 = v4n; lrv = lrvn;
        __syncthreads();                               // C
    }
}

// ------- post-norm + gelu gate -> pre-split G (hi/lo) for the wo GEMM ---------
__global__ __launch_bounds__(256) void combine_kernel(
    const float* __restrict__ pns, const float* __restrict__ pnb,
    const float* __restrict__ scan_in, const float* __restrict__ gatef,
    float* __restrict__ Gh, float* __restrict__ Gl)
{
    __shared__ float red[16];
    __shared__ float muv, istdv;
    int row = blockIdx.x;
    int t = threadIdx.x;
    const float* x = scan_in + (size_t)row * WD;
    float v0 = x[t], v1 = x[t + 256], v2 = x[t + 512];
    float s = v0 + v1 + v2;
    float s2 = v0 * v0 + v1 * v1 + v2 * v2;
#pragma unroll
    for (int o = 16; o > 0; o >>= 1) {
        s  += __shfl_xor_sync(0xffffffffu, s, o);
        s2 += __shfl_xor_sync(0xffffffffu, s2, o);
    }
    if ((t & 31) == 0) { red[t >> 5] = s; red[8 + (t >> 5)] = s2; }
    __syncthreads();
    if (t == 0) {
        float a = 0.f, b2 = 0.f;
        for (int j = 0; j < 8; j++) { a += red[j]; b2 += red[8 + j]; }
        float mu = a * (1.0f / 768.0f);
        float var = b2 * (1.0f / 768.0f) - mu * mu;
        muv = mu;
        istdv = 1.0f / sqrtf(var + LN_EPS);
    }
    __syncthreads();
    float mu = muv, istd = istdv;
    const float* gp = gatef + (size_t)row * WD;
    float* Ghp = Gh + (size_t)row * WD;
    float* Glp = Gl + (size_t)row * WD;
    float vv[3] = {v0, v1, v2};
#pragma unroll
    for (int j = 0; j < 3; j++) {
        int c = t + j * 256;
        float z = pns[c] * ((vv[j] - mu) * istd) + pnb[c];
        float gx = gp[c];
        float inner = 0.7978845608028654f * (gx + 0.044715f * gx * gx * gx);
        float gl = 0.5f * gx * (1.0f + tanhf(inner));
        float g = gl * z;
        float hh, ll;
        split_tf32s(g, hh, ll);
        Ghp[c] = hh;
        Glp[c] = ll;
    }
}

// ---------------- launch ------------------------------------------------------
extern "C" void kernel_launch(void* const* d_in, const int* in_sizes, int n_in,
                              void* d_out, int out_size)
{
    const float* hidden = (const float*)d_in[0];
    const float* wq  = (const float*)d_in[1];
    const float* wv  = (const float*)d_in[2];
    const float* wo  = (const float*)d_in[3];
    const float* wg  = (const float*)d_in[4];
    const float* ckq = (const float*)d_in[5];
    const float* cbq = (const float*)d_in[6];
    const float* ckk = (const float*)d_in[7];
    const float* cbk = (const float*)d_in[8];
    const float* W1  = (const float*)d_in[9];
    const float* b1  = (const float*)d_in[10];
    const float* nsc = (const float*)d_in[11];
    const float* nbi = (const float*)d_in[12];
    const float* lrk = (const float*)d_in[13];
    const float* lrb = (const float*)d_in[14];
    const float* lti = (const float*)d_in[15];
    const float* pns = (const float*)d_in[16];
    const float* pnb = (const float*)d_in[17];
    float* out = (float*)d_out;

    float *xqk, *xv, *gate, *XQ, *XK, *XVr, *lr, *scan, *Ah, *Al, *Bh, *Bl;
    cudaGetSymbolAddress((void**)&xqk,  g_xqk);
    cudaGetSymbolAddress((void**)&xv,   g_xv);
    cudaGetSymbolAddress((void**)&gate, g_gate);
    cudaGetSymbolAddress((void**)&XQ,   g_XQ);
    cudaGetSymbolAddress((void**)&XK,   g_XK);
    cudaGetSymbolAddress((void**)&XVr,  g_XVr);
    cudaGetSymbolAddress((void**)&lr,   g_lr);
    cudaGetSymbolAddress((void**)&scan, g_scan);
    cudaGetSymbolAddress((void**)&Ah,   g_Ah);
    cudaGetSymbolAddress((void**)&Al,   g_Al);
    cudaGetSymbolAddress((void**)&Bh,   g_Bh);
    cudaGetSymbolAddress((void**)&Bl,   g_Bl);

    static int smem_set = 0;
    if (!smem_set) {
        cudaFuncSetAttribute(gemm_tf32_kernel,
                             cudaFuncAttributeMaxDynamicSharedMemorySize, GEMM_SMEM_BYTES);
        smem_set = 1;
    }

    const int NH = R_TOT * WD / 4;
    const int NW = WD * WD / 4;
    dim3 gg(WD / 128, R_TOT / 128);

    lr_kernel<<<R_TOT / 8, 256>>>(hidden, lrk, lrb, lr);
    split_kernel<<<(NH + 255) / 256, 256>>>(hidden, Ah, Al, NH);
    split_kernel<<<(NW + 255) / 256, 256>>>(wq, Bh, Bl, NW);
    gemm_tf32_kernel<<<gg, 256, GEMM_SMEM_BYTES>>>(Ah, Al, Bh, Bl, xqk, R_TOT, WD, WD);
    split_kernel<<<(NW + 255) / 256, 256>>>(wv, Bh, Bl, NW);
    gemm_tf32_kernel<<<gg, 256, GEMM_SMEM_BYTES>>>(Ah, Al, Bh, Bl, xv, R_TOT, WD, WD);
    split_kernel<<<(NW + 255) / 256, 256>>>(wg, Bh, Bl, NW);
    gemm_tf32_kernel<<<gg, 256, GEMM_SMEM_BYTES>>>(Ah, Al, Bh, Bl, gate, R_TOT, WD, WD);
    convrope_kernel<<<(R_TOT * 384 + 255) / 256, 256>>>(xqk, xv, ckq, cbq, ckk, cbk, XQ, XK, XVr);
    scan_kernel<<<NB * NHEADS, 256>>>(W1, b1, nsc, nbi, lti, XQ, XK, XVr, lr, scan);
    // combine writes pre-split G straight into Ah/Al (hidden splits no longer needed)
    combine_kernel<<<R_TOT, 256>>>(pns, pnb, scan, gate, Ah, Al);
    split_kernel<<<(NW + 255) / 256, 256>>>(wo, Bh, Bl, NW);
    gemm_tf32_kernel<<<gg, 256, GEMM_SMEM_BYTES>>>(Ah, Al, Bh, Bl, out, R_TOT, WD, WD);
}

// round 16
// speedup vs baseline: 1.6146x; 1.6146x over previous
#include <cuda_runtime.h>
#include <math.h>
#include <stdint.h>

#define R_TOT 16384
#define WD 768
#define NHEADS 12
#define HDIM 64
#define NMB 256
#define MB 16
#define SEQ 4096
#define NB 4
#define LN_EPS 1e-6f

// ---------------- scratch (device globals; no allocation allowed) -------------
__device__ float g_xqk [R_TOT * WD];                 // hidden@wq, later reused as G
__device__ float g_xv  [R_TOT * WD];                 // hidden@wv
__device__ float g_gate[R_TOT * WD];                 // hidden@wg (pre-gelu)
__device__ float g_XQ  [NB * NHEADS * NMB * MB * HDIM];
__device__ float g_XK  [NB * NHEADS * NMB * MB * HDIM];
__device__ float g_XVr [NB * NHEADS * NMB * MB * HDIM];
__device__ float g_lr  [NB * NHEADS * NMB * MB];
__device__ float g_scan[R_TOT * WD];

// ============ split-tf32 tensor-core GEMM: C[M,N] = A[M,K]@B[K,N] =============
// (exact R6 kernel — known best: 334us/GEMM)

__device__ __forceinline__ void split_tf32(float x, uint32_t& hi, uint32_t& lo) {
    float h;
    asm("cvt.rna.tf32.f32 %0, %1;" : "=f"(h) : "f"(x));
    float l = x - h;
    float l2;
    asm("cvt.rna.tf32.f32 %0, %1;" : "=f"(l2) : "f"(l));
    hi = __float_as_uint(h);
    lo = __float_as_uint(l2);
}

__device__ __forceinline__ void mma_tf32(float* c, const uint32_t* a, const uint32_t* b) {
    asm volatile(
        "mma.sync.aligned.m16n8k8.row.col.f32.tf32.tf32.f32 "
        "{%0,%1,%2,%3}, {%4,%5,%6,%7}, {%8,%9}, {%0,%1,%2,%3};"
        : "+f"(c[0]), "+f"(c[1]), "+f"(c[2]), "+f"(c[3])
        : "r"(a[0]), "r"(a[1]), "r"(a[2]), "r"(a[3]), "r"(b[0]), "r"(b[1]));
}

#define CP16(smem_u32, gptr) \
    asm volatile("cp.async.cg.shared.global [%0], [%1], 16;" :: "r"(smem_u32), "l"(gptr))

#define SA_STRIDE 20
#define SB_STRIDE 136

__global__ __launch_bounds__(256) void gemm_tf32_kernel(
    const float* __restrict__ A, const float* __restrict__ B,
    float* __restrict__ C, int M, int N, int K)
{
    __shared__ float sA[2][128 * SA_STRIDE];
    __shared__ float sB[2][16 * SB_STRIDE];

    const int tid  = threadIdx.x;
    const int wid  = tid >> 5;
    const int lane = tid & 31;
    const int lr   = lane >> 2;
    const int lc   = lane & 3;
    const int warpM = wid >> 2;
    const int warpN = wid & 3;

    const int NT = K / 16;

    const float* Ab = A + (size_t)(blockIdx.y * 128) * K;
    const float* Bb = B + blockIdx.x * 128;

    uint32_t sA_u32 = (uint32_t)__cvta_generic_to_shared(&sA[0][0]);
    uint32_t sB_u32 = (uint32_t)__cvta_generic_to_shared(&sB[0][0]);

    const int aRow0 = tid >> 2;
    const int aC4   = (tid & 3) * 4;
    const int bRow0 = tid >> 5;
    const int bC4   = (tid & 31) * 4;

    float acc[4][4][4];
#pragma unroll
    for (int m = 0; m < 4; m++)
#pragma unroll
        for (int n = 0; n < 4; n++)
#pragma unroll
            for (int e = 0; e < 4; e++) acc[m][n][e] = 0.f;

    {
        const float* ag = Ab + (size_t)aRow0 * K + aC4;
        CP16(sA_u32 + (aRow0 * SA_STRIDE + aC4) * 4, ag);
        CP16(sA_u32 + ((aRow0 + 64) * SA_STRIDE + aC4) * 4, ag + (size_t)64 * K);
        const float* bg = Bb + (size_t)bRow0 * N + bC4;
        CP16(sB_u32 + (bRow0 * SB_STRIDE + bC4) * 4, bg);
        CP16(sB_u32 + ((bRow0 + 8) * SB_STRIDE + bC4) * 4, bg + (size_t)8 * N);
        asm volatile("cp.async.commit_group;");
    }

    for (int kt = 0; kt < NT; kt++) {
        const int cur = kt & 1;
        if (kt + 1 < NT) {
            const int nxt = (kt + 1) & 1;
            uint32_t sAn = sA_u32 + nxt * 128 * SA_STRIDE * 4;
            uint32_t sBn = sB_u32 + nxt * 16 * SB_STRIDE * 4;
            const float* ag = Ab + (size_t)aRow0 * K + (kt + 1) * 16 + aC4;
            CP16(sAn + (aRow0 * SA_STRIDE + aC4) * 4, ag);
            CP16(sAn + ((aRow0 + 64) * SA_STRIDE + aC4) * 4, ag + (size_t)64 * K);
            const float* bg = Bb + (size_t)((kt + 1) * 16 + bRow0) * N + bC4;
            CP16(sBn + (bRow0 * SB_STRIDE + bC4) * 4, bg);
            CP16(sBn + ((bRow0 + 8) * SB_STRIDE + bC4) * 4, bg + (size_t)8 * N);
            asm volatile("cp.async.commit_group;");
            asm volatile("cp.async.wait_group 1;");
        } else {
            asm volatile("cp.async.wait_group 0;");
        }
        __syncthreads();

        const float* cA = &sA[cur][0];
        const float* cB = &sB[cur][0];
#pragma unroll
        for (int ks = 0; ks < 2; ks++) {
            uint32_t ahi[4][4], alo[4][4];
#pragma unroll
            for (int m = 0; m < 4; m++) {
                int r0 = warpM * 64 + m * 16 + lr;
                int c0 = ks * 8 + lc;
                split_tf32(cA[r0 * SA_STRIDE + c0],            ahi[m][0], alo[m][0]);
                split_tf32(cA[(r0 + 8) * SA_STRIDE + c0],      ahi[m][1], alo[m][1]);
                split_tf32(cA[r0 * SA_STRIDE + c0 + 4],        ahi[m][2], alo[m][2]);
                split_tf32(cA[(r0 + 8) * SA_STRIDE + c0 + 4],  ahi[m][3], alo[m][3]);
            }
            uint32_t bhi[4][2], blo[4][2];
#pragma unroll
            for (int n = 0; n < 4; n++) {
                int cc = warpN * 32 + n * 8 + lr;
                int r0 = ks * 8 + lc;
                split_tf32(cB[r0 * SB_STRIDE + cc],       bhi[n][0], blo[n][0]);
                split_tf32(cB[(r0 + 4) * SB_STRIDE + cc], bhi[n][1], blo[n][1]);
            }
#pragma unroll
            for (int m = 0; m < 4; m++)
#pragma unroll
                for (int n = 0; n < 4; n++) {
                    mma_tf32(acc[m][n], ahi[m], bhi[n]);
                    mma_tf32(acc[m][n], ahi[m], blo[n]);
                    mma_tf32(acc[m][n], alo[m], bhi[n]);
                }
        }
        __syncthreads();
    }

#pragma unroll
    for (int m = 0; m < 4; m++) {
        int row = blockIdx.y * 128 + warpM * 64 + m * 16 + lr;
#pragma unroll
        for (int n = 0; n < 4; n++) {
            int col = blockIdx.x * 128 + warpN * 32 + n * 8 + 2 * lc;
            float* cp = C + (size_t)row * N + col;
            *(float2*)cp = make_float2(acc[m][n][0], acc[m][n][1]);
            *(float2*)(cp + (size_t)8 * N) = make_float2(acc[m][n][2], acc[m][n][3]);
        }
    }
}

// ---------------- ttt_lr ------------------------------------------------------
__global__ __launch_bounds__(256) void lr_kernel(
    const float* __restrict__ hidden, const float* __restrict__ lrk,
    const float* __restrict__ lrb, float* __restrict__ out)
{
    int row = blockIdx.x * 8 + (threadIdx.x >> 5);
    int lane = threadIdx.x & 31;
    if (row >= R_TOT) return;
    const float* hr = hidden + (size_t)row * WD;
    float acc[NHEADS];
#pragma unroll
    for (int h = 0; h < NHEADS; h++) acc[h] = 0.f;
    for (int w = lane; w < WD; w += 32) {
        float hv = hr[w];
#pragma unroll
        for (int h = 0; h < NHEADS; h++) acc[h] += hv * lrk[h * WD + w];
    }
#pragma unroll
    for (int h = 0; h < NHEADS; h++) {
#pragma unroll
        for (int o = 16; o > 0; o >>= 1)
            acc[h] += __shfl_xor_sync(0xffffffffu, acc[h], o);
    }
    if (lane < NHEADS) {
        float x = acc[lane] + lrb[lane];
        float v = (1.0f / (1.0f + expf(-x))) * (1.0f / 64.0f);
        int b = row >> 12;
        int n = row & 4095;
        int nm = n >> 4, m = n & 15;
        out[(((size_t)b * NHEADS + lane) * NMB + nm) * MB + m] = v;
    }
}

// ---------------- causal dwconv(width 4) + RoPE + reorder ---------------------
__global__ __launch_bounds__(256) void convrope_kernel(
    const float* __restrict__ xqk, const float* __restrict__ xv,
    const float* __restrict__ kq, const float* __restrict__ bq,
    const float* __restrict__ kk, const float* __restrict__ bk,
    float* __restrict__ XQr, float* __restrict__ XKr, float* __restrict__ XVr)
{
    int idx = blockIdx.x * blockDim.x + threadIdx.x;
    if (idx >= R_TOT * 384) return;
    int c2 = idx % 384;
    int row = idx / 384;
    int c = c2 * 2;
    int n = row & 4095;
    int b = row >> 12;

    float q0 = bq[c], q1 = bq[c + 1];
    float k0 = bk[c], k1 = bk[c + 1];
#pragma unroll
    for (int t = 0; t < 4; t++) {
        int nn = n - 3 + t;
        if (nn >= 0) {
            const float* xr = xqk + ((size_t)(b * SEQ + nn)) * WD + c;
            float x0 = xr[0], x1 = xr[1];
            q0 += kq[t * WD + c] * x0;     q1 += kq[t * WD + c + 1] * x1;
            k0 += kk[t * WD + c] * x0;     k1 += kk[t * WD + c + 1] * x1;
        }
    }
    int h = c >> 6;
    int d = c & 63;
    int fi = d >> 1;
    int pos = n & 15;
    float freq = exp2f(-((float)(2 * fi) * (1.0f / 64.0f)) * 13.2877123795f);
    float ang = (float)pos * freq;
    float cs = cosf(ang), sn = sinf(ang);

    float qe = q0 * cs - q1 * sn;
    float qo = q0 * sn + q1 * cs;
    float ke = k0 * cs - k1 * sn;
    float ko = k0 * sn + k1 * cs;

    int nm = n >> 4, m = n & 15;
    size_t off = ((((size_t)b * NHEADS + h) * NMB + nm) * MB + m) * HDIM + d;
    XQr[off] = qe;  XQr[off + 1] = qo;
    XKr[off] = ke;  XKr[off + 1] = ko;
    const float* xvp = xv + (size_t)row * WD + c;
    XVr[off] = xvp[0];  XVr[off + 1] = xvp[1];
}

// ---------------- the TTT scan (exact R6) -------------------------------------
#define XS 68   // XQ/XK tile row stride

__global__ __launch_bounds__(256) void scan_kernel(
    const float* __restrict__ W1g, const float* __restrict__ b1g,
    const float* __restrict__ glng, const float* __restrict__ blng,
    const float* __restrict__ lti,
    const float* __restrict__ XQg, const float* __restrict__ XKg,
    const float* __restrict__ XVg, const float* __restrict__ lrg,
    float* __restrict__ scan_out)
{
    __shared__ float W1s[64 * 64];
    __shared__ float b1s[64];
    __shared__ float XQs[16 * XS];
    __shared__ float XKs[16 * XS];
    __shared__ float Ts [16 * 64];
    __shared__ float grads[16 * 64];
    __shared__ float Attns[16 * 17];
    __shared__ float lrs[16];
    __shared__ float tis[16];
    __shared__ float gln[64], bln[64];

    const int bh = blockIdx.x;
    const int h = bh % NHEADS;
    const int b = bh / NHEADS;
    const int t = threadIdx.x;

    {
        const float* w1p = W1g + (size_t)h * 64 * 64;
        for (int j = t; j < 4096; j += 256) W1s[j] = w1p[j];
        if (t < 64) {
            b1s[t] = b1g[h * 64 + t];
            gln[t] = glng[h * 64 + t];
            bln[t] = blng[h * 64 + t];
        }
        if (t < 16) tis[t] = fmaxf(1.0f / (float)(t + 1) + lti[t], 0.0f);
    }
    __syncthreads();

    const int i  = t >> 4;
    const int cg = t & 15;
    const int d0 = cg * 4;

    const float gv0 = gln[d0], gv1 = gln[d0 + 1], gv2 = gln[d0 + 2], gv3 = gln[d0 + 3];
    const float bv0 = bln[d0], bv1 = bln[d0 + 1], bv2 = bln[d0 + 2], bv3 = bln[d0 + 3];
    const float ti_i = tis[i];
    const float le15 = tis[15];

    const float* XQb = XQg + (size_t)bh * NMB * MB * HDIM;
    const float* XKb = XKg + (size_t)bh * NMB * MB * HDIM;
    const float* XVb = XVg + (size_t)bh * NMB * MB * HDIM;
    const float* lrbp = lrg + (size_t)bh * NMB * MB;
    float* outb = scan_out + (size_t)b * SEQ * WD + h * HDIM;

    size_t tb = (size_t)i * HDIM + d0;
    float4 q4 = *(const float4*)(XQb + tb);
    float4 k4 = *(const float4*)(XKb + tb);
    float4 v4 = *(const float4*)(XVb + tb);
    float lrv = (t < 16) ? lrbp[t] : 0.f;

    for (int s = 0; s < NMB; s++) {
        *(float4*)&XQs[i * XS + d0] = q4;
        *(float4*)&XKs[i * XS + d0] = k4;
        *(float4*)&Ts[i * 64 + d0] = make_float4(v4.x - k4.x, v4.y - k4.y, v4.z - k4.z, v4.w - k4.w);
        if (t < 16) lrs[t] = lrv;
        __syncthreads();                               // A

        float4 q4n, k4n, v4n; float lrvn = 0.f;
        if (s + 1 < NMB) {
            size_t tb2 = (size_t)(s + 1) * MB * HDIM + i * HDIM + d0;
            q4n = *(const float4*)(XQb + tb2);
            k4n = *(const float4*)(XKb + tb2);
            v4n = *(const float4*)(XVb + tb2);
            if (t < 16) lrvn = lrbp[(s + 1) * MB + t];
        }

        float b1x = b1s[d0], b1y = b1s[d0 + 1], b1z = b1s[d0 + 2], b1w = b1s[d0 + 3];
        float zx = b1x, zy = b1y, zz = b1z, zw = b1w;
        float ax = b1x, ay = b1y, az = b1z, aw = b1w;
        float at = 0.f;
#pragma unroll
        for (int k0 = 0; k0 < 64; k0 += 4) {
            float4 xkv = *(const float4*)&XKs[i * XS + k0];
            float4 xqv = *(const float4*)&XQs[i * XS + k0];
            float4 xka = *(const float4*)&XKs[cg * XS + k0];
            at += xqv.x * xka.x + xqv.y * xka.y + xqv.z * xka.z + xqv.w * xka.w;
            {
                float4 w = *(const float4*)&W1s[(k0 + 0) * 64 + d0];
                zx += xkv.x * w.x; zy += xkv.x * w.y; zz += xkv.x * w.z; zw += xkv.x * w.w;
                ax += xqv.x * w.x; ay += xqv.x * w.y; az += xqv.x * w.z; aw += xqv.x * w.w;
            }
            {
                float4 w = *(const float4*)&W1s[(k0 + 1) * 64 + d0];
                zx += xkv.y * w.x; zy += xkv.y * w.y; zz += xkv.y * w.z; zw += xkv.y * w.w;
                ax += xqv.y * w.x; ay += xqv.y * w.y; az += xqv.y * w.z; aw += xqv.y * w.w;
            }
            {
                float4 w = *(const float4*)&W1s[(k0 + 2) * 64 + d0];
                zx += xkv.z * w.x; zy += xkv.z * w.y; zz += xkv.z * w.z; zw += xkv.z * w.w;
                ax += xqv.z * w.x; ay += xqv.z * w.y; az += xqv.z * w.z; aw += xqv.z * w.w;
            }
            {
                float4 w = *(const float4*)&W1s[(k0 + 3) * 64 + d0];
                zx += xkv.w * w.x; zy += xkv.w * w.y; zz += xkv.w * w.z; zw += xkv.w * w.w;
                ax += xqv.w * w.x; ay += xqv.w * w.y; az += xqv.w * w.z; aw += xqv.w * w.w;
            }
        }
        Attns[i * 17 + cg] = at;

        float sum = zx + zy + zz + zw;
        sum += __shfl_xor_sync(0xffffffffu, sum, 1);
        sum += __shfl_xor_sync(0xffffffffu, sum, 2);
        sum += __shfl_xor_sync(0xffffffffu, sum, 4);
        sum += __shfl_xor_sync(0xffffffffu, sum, 8);
        float mu = sum * (1.0f / 64.0f);
        float cx = zx - mu, cy = zy - mu, cz = zz - mu, cw = zw - mu;
        float s2 = cx * cx + cy * cy + cz * cz + cw * cw;
        s2 += __shfl_xor_sync(0xffffffffu, s2, 1);
        s2 += __shfl_xor_sync(0xffffffffu, s2, 2);
        s2 += __shfl_xor_sync(0xffffffffu, s2, 4);
        s2 += __shfl_xor_sync(0xffffffffu, s2, 8);
        float istd = 1.0f / sqrtf(s2 * (1.0f / 64.0f) + LN_EPS);
        float xh0 = cx * istd, xh1 = cy * istd, xh2 = cz * istd, xh3 = cw * istd;
        float4 tt = *(const float4*)&Ts[i * 64 + d0];
        float g0 = (gv0 * xh0 + bv0 - tt.x) * gv0;
        float g1 = (gv1 * xh1 + bv1 - tt.y) * gv1;
        float g2 = (gv2 * xh2 + bv2 - tt.z) * gv2;
        float g3 = (gv3 * xh3 + bv3 - tt.w) * gv3;
        float sg = g0 + g1 + g2 + g3;
        sg += __shfl_xor_sync(0xffffffffu, sg, 1);
        sg += __shfl_xor_sync(0xffffffffu, sg, 2);
        sg += __shfl_xor_sync(0xffffffffu, sg, 4);
        sg += __shfl_xor_sync(0xffffffffu, sg, 8);
        float sgx = g0 * xh0 + g1 * xh1 + g2 * xh2 + g3 * xh3;
        sgx += __shfl_xor_sync(0xffffffffu, sgx, 1);
        sgx += __shfl_xor_sync(0xffffffffu, sgx, 2);
        sgx += __shfl_xor_sync(0xffffffffu, sgx, 4);
        sgx += __shfl_xor_sync(0xffffffffu, sgx, 8);
        float cf = istd * (1.0f / 64.0f);
        *(float4*)&grads[i * 64 + d0] = make_float4(
            (64.f * g0 - sg - xh0 * sgx) * cf,
            (64.f * g1 - sg - xh1 * sgx) * cf,
            (64.f * g2 - sg - xh2 * sgx) * cf,
            (64.f * g3 - sg - xh3 * sgx) * cf);
        __syncthreads();                               // B

        for (int jj = 0; jj <= i; jj++) {
            float c = ti_i * lrs[jj] * (Attns[i * 17 + jj] + 1.0f);
            float4 gr = *(const float4*)&grads[jj * 64 + d0];
            ax -= c * gr.x;  ay -= c * gr.y;  az -= c * gr.z;  aw -= c * gr.w;
        }
        float su = ax + ay + az + aw;
        su += __shfl_xor_sync(0xffffffffu, su, 1);
        su += __shfl_xor_sync(0xffffffffu, su, 2);
        su += __shfl_xor_sync(0xffffffffu, su, 4);
        su += __shfl_xor_sync(0xffffffffu, su, 8);
        float mu2 = su * (1.0f / 64.0f);
        float ex = ax - mu2, ey = ay - mu2, ez = az - mu2, ew = aw - mu2;
        float v2 = ex * ex + ey * ey + ez * ez + ew * ew;
        v2 += __shfl_xor_sync(0xffffffffu, v2, 1);
        v2 += __shfl_xor_sync(0xffffffffu, v2, 2);
        v2 += __shfl_xor_sync(0xffffffffu, v2, 4);
        v2 += __shfl_xor_sync(0xffffffffu, v2, 8);
        float istd2 = 1.0f / sqrtf(v2 * (1.0f / 64.0f) + LN_EPS);
        *(float4*)(outb + (size_t)(s * MB + i) * WD + d0) = make_float4(
            q4.x + gv0 * (ex * istd2) + bv0,
            q4.y + gv1 * (ey * istd2) + bv1,
            q4.z + gv2 * (ez * istd2) + bv2,
            q4.w + gv3 * (ew * istd2) + bv3);

        {
            float4 w0 = *(const float4*)&W1s[(4 * i + 0) * 64 + d0];
            float4 w1 = *(const float4*)&W1s[(4 * i + 1) * 64 + d0];
            float4 w2 = *(const float4*)&W1s[(4 * i + 2) * 64 + d0];
            float4 w3 = *(const float4*)&W1s[(4 * i + 3) * 64 + d0];
#pragma unroll
            for (int ii = 0; ii < 16; ii++) {
                float lg = le15 * lrs[ii];
                float4 xk4 = *(const float4*)&XKs[ii * XS + 4 * i];
                float4 gr  = *(const float4*)&grads[ii * 64 + d0];
                float c0 = lg * xk4.x, c1 = lg * xk4.y, c2 = lg * xk4.z, c3 = lg * xk4.w;
                w0.x -= c0 * gr.x; w0.y -= c0 * gr.y; w0.z -= c0 * gr.z; w0.w -= c0 * gr.w;
                w1.x -= c1 * gr.x; w1.y -= c1 * gr.y; w1.z -= c1 * gr.z; w1.w -= c1 * gr.w;
                w2.x -= c2 * gr.x; w2.y -= c2 * gr.y; w2.z -= c2 * gr.z; w2.w -= c2 * gr.w;
                w3.x -= c3 * gr.x; w3.y -= c3 * gr.y; w3.z -= c3 * gr.z; w3.w -= c3 * gr.w;
            }
            *(float4*)&W1s[(4 * i + 0) * 64 + d0] = w0;
            *(float4*)&W1s[(4 * i + 1) * 64 + d0] = w1;
            *(float4*)&W1s[(4 * i + 2) * 64 + d0] = w2;
            *(float4*)&W1s[(4 * i + 3) * 64 + d0] = w3;
        }
        if (i == 0) {
            float4 bb = *(const float4*)&b1s[d0];
#pragma unroll
            for (int ii = 0; ii < 16; ii++) {
                float lg = le15 * lrs[ii];
                float4 gr = *(const float4*)&grads[ii * 64 + d0];
                bb.x -= lg * gr.x; bb.y -= lg * gr.y; bb.z -= lg * gr.z; bb.w -= lg * gr.w;
            }
            *(float4*)&b1s[d0] = bb;
        }

        q4 = q4n; k4 = k4n; v4 = v4n; lrv = lrvn;
        __syncthreads();                               // C
    }
}

// ---------------- post-norm + gelu gate -> G ---------------------------------
__global__ __launch_bounds__(256) void combine_kernel(
    const float* __restrict__ pns, const float* __restrict__ pnb,
    const float* __restrict__ scan_in, const float* __restrict__ gatef,
    float* __restrict__ G)
{
    __shared__ float red[16];
    __shared__ float muv, istdv;
    int row = blockIdx.x;
    int t = threadIdx.x;
    const float* x = scan_in + (size_t)row * WD;
    float v0 = x[t], v1 = x[t + 256], v2 = x[t + 512];
    float s = v0 + v1 + v2;
    float s2 = v0 * v0 + v1 * v1 + v2 * v2;
#pragma unroll
    for (int o = 16; o > 0; o >>= 1) {
        s  += __shfl_xor_sync(0xffffffffu, s, o);
        s2 += __shfl_xor_sync(0xffffffffu, s2, o);
    }
    if ((t & 31) == 0) { red[t >> 5] = s; red[8 + (t >> 5)] = s2; }
    __syncthreads();
    if (t == 0) {
        float a = 0.f, b2 = 0.f;
        for (int j = 0; j < 8; j++) { a += red[j]; b2 += red[8 + j]; }
        float mu = a * (1.0f / 768.0f);
        float var = b2 * (1.0f / 768.0f) - mu * mu;
        muv = mu;
        istdv = 1.0f / sqrtf(var + LN_EPS);
    }
    __syncthreads();
    float mu = muv, istd = istdv;
    const float* gp = gatef + (size_t)row * WD;
    float* Gp = G + (size_t)row * WD;
    float vv[3] = {v0, v1, v2};
#pragma unroll
    for (int j = 0; j < 3; j++) {
        int c = t + j * 256;
        float z = pns[c] * ((vv[j] - mu) * istd) + pnb[c];
        float gx = gp[c];
        float inner = 0.7978845608028654f * (gx + 0.044715f * gx * gx * gx);
        float gl = 0.5f * gx * (1.0f + tanhf(inner));
        Gp[c] = gl * z;
    }
}

// ---------------- launch: fork-join overlap -----------------------------------
// s0 (default): wq -> wv -> convrope -> [wait lr] scan -> [wait gate] combine -> wo
// s1 (side):    lr (under wq) ... [wait convrope-done] wg (under scan)
extern "C" void kernel_launch(void* const* d_in, const int* in_sizes, int n_in,
                              void* d_out, int out_size)
{
    const float* hidden = (const float*)d_in[0];
    const float* wq  = (const float*)d_in[1];
    const float* wv  = (const float*)d_in[2];
    const float* wo  = (const float*)d_in[3];
    const float* wg  = (const float*)d_in[4];
    const float* ckq = (const float*)d_in[5];
    const float* cbq = (const float*)d_in[6];
    const float* ckk = (const float*)d_in[7];
    const float* cbk = (const float*)d_in[8];
    const float* W1  = (const float*)d_in[9];
    const float* b1  = (const float*)d_in[10];
    const float* nsc = (const float*)d_in[11];
    const float* nbi = (const float*)d_in[12];
    const float* lrk = (const float*)d_in[13];
    const float* lrb = (const float*)d_in[14];
    const float* lti = (const float*)d_in[15];
    const float* pns = (const float*)d_in[16];
    const float* pnb = (const float*)d_in[17];
    float* out = (float*)d_out;

    float *xqk, *xv, *gate, *XQ, *XK, *XVr, *lr, *scan;
    cudaGetSymbolAddress((void**)&xqk,  g_xqk);
    cudaGetSymbolAddress((void**)&xv,   g_xv);
    cudaGetSymbolAddress((void**)&gate, g_gate);
    cudaGetSymbolAddress((void**)&XQ,   g_XQ);
    cudaGetSymbolAddress((void**)&XK,   g_XK);
    cudaGetSymbolAddress((void**)&XVr,  g_XVr);
    cudaGetSymbolAddress((void**)&lr,   g_lr);
    cudaGetSymbolAddress((void**)&scan, g_scan);

    static cudaStream_t s1;
    static cudaEvent_t evRoot, evLr, evConv, evGate;
    static int init = 0;
    if (!init) {
        cudaStreamCreateWithFlags(&s1, cudaStreamNonBlocking);
        cudaEventCreateWithFlags(&evRoot, cudaEventDisableTiming);
        cudaEventCreateWithFlags(&evLr,   cudaEventDisableTiming);
        cudaEventCreateWithFlags(&evConv, cudaEventDisableTiming);
        cudaEventCreateWithFlags(&evGate, cudaEventDisableTiming);
        init = 1;
    }

    dim3 gg(WD / 128, R_TOT / 128);

    // fork side stream
    cudaEventRecord(evRoot, 0);
    cudaStreamWaitEvent(s1, evRoot, 0);

    // s1: lr (needs only hidden) — runs under the wq GEMM
    lr_kernel<<<R_TOT / 8, 256, 0, s1>>>(hidden, lrk, lrb, lr);
    cudaEventRecord(evLr, s1);

    // s0: the two GEMMs feeding convrope
    gemm_tf32_kernel<<<gg, 256>>>(hidden, wq, xqk, R_TOT, WD, WD);
    gemm_tf32_kernel<<<gg, 256>>>(hidden, wv, xv, R_TOT, WD, WD);
    convrope_kernel<<<(R_TOT * 384 + 255) / 256, 256>>>(xqk, xv, ckq, cbq, ckk, cbk, XQ, XK, XVr);
    cudaEventRecord(evConv, 0);

    // s0: scan needs lr results
    cudaStreamWaitEvent(0, evLr, 0);
    scan_kernel<<<NB * NHEADS, 256>>>(W1, b1, nsc, nbi, lti, XQ, XK, XVr, lr, scan);

    // s1: wg GEMM gated to start when the scan starts (after convrope) — hides under it
    cudaStreamWaitEvent(s1, evConv, 0);
    gemm_tf32_kernel<<<gg, 256, 0, s1>>>(hidden, wg, gate, R_TOT, WD, WD);
    cudaEventRecord(evGate, s1);

    // s0: join — combine needs gate
    cudaStreamWaitEvent(0, evGate, 0);
    combine_kernel<<<R_TOT, 256>>>(pns, pnb, scan, gate, xqk);
    gemm_tf32_kernel<<<gg, 256>>>(xqk, wo, out, R_TOT, WD, WD);
}